// round 2
// baseline (speedup 1.0000x reference)
#include <cuda_runtime.h>
#include <cstdint>
#include <cstring>
#include <math.h>

// ---------------------------------------------------------------------------
// Problem constants
// ---------------------------------------------------------------------------
#define BGR   512
#define NPG   64
#define CNUM  8
#define MPG   128
#define CN    256
#define CE    64
#define EPG   200            // MPG + CNUM + NPG

#define NE_NODES (BGR*MPG)        // 65536 br nodes
#define NE_EDGES (BGR*MPG*4)      // 262144 br edges
#define NN_NODES (BGR*NPG)        // 32768 nodes
#define NN_EDGES (BGR*EPG)        // 102400 edges

// output layout: out2 | ei | br | super_node
#define OFF_OUT2 0
#define OFF_EI   ((size_t)NN_NODES*CN)                    // 8388608
#define OFF_BR   (OFF_EI + (size_t)NN_EDGES*CE)           // 14942208
#define OFF_SN   (OFF_BR + (size_t)NE_NODES*CE)           // 19136512

// ---------------------------------------------------------------------------
// Scratch (device globals: allocation-free)
// ---------------------------------------------------------------------------
__device__ float g_qE[(size_t)NE_NODES*CE];
__device__ float g_kE[(size_t)NE_NODES*CE];
__device__ float g_vE[(size_t)NE_NODES*CE];
__device__ float g_accE[(size_t)NE_NODES*CE];
__device__ float g_br1[(size_t)NE_NODES*CE];
__device__ float g_logE[(size_t)NE_EDGES*4];
__device__ float g_maxE[(size_t)NE_NODES*4];
__device__ float g_sumE[(size_t)NE_NODES*4];

__device__ float g_ei1[(size_t)NN_EDGES*CE];
__device__ float g_ef[(size_t)NN_EDGES*CN];
__device__ float g_qN[(size_t)NN_NODES*CN];
__device__ float g_kN[(size_t)NN_NODES*CN];
__device__ float g_vN[(size_t)NN_NODES*CN];
__device__ float g_accN[(size_t)NN_NODES*CN];
__device__ float g_out1[(size_t)NN_NODES*CN];
__device__ float g_logN[(size_t)NN_EDGES*4];
__device__ float g_maxN[(size_t)NN_NODES*4];
__device__ float g_sumN[(size_t)NN_NODES*4];

__device__ float g_bnsum[CN];
__device__ float g_bnsq[CN];
__device__ float g_mu[CN];
__device__ float g_rstd[CN];

// ---------------------------------------------------------------------------
// Helpers
// ---------------------------------------------------------------------------
__device__ __forceinline__ void atomicMaxF(float* addr, float v) {
    if (v >= 0.f) atomicMax((int*)addr, __float_as_int(v));
    else          atomicMin((unsigned int*)addr, __float_as_uint(v));
}

__global__ void fill_f(float* p, int n, float v) {
    int i = blockIdx.x * blockDim.x + threadIdx.x;
    if (i < n) p[i] = v;
}

// ---------------------------------------------------------------------------
// SGEMM: C[M,N] = A[M,K] @ W[K,N].  M,N,K multiples of 16; N,K mult of 64 here.
// 64x64 block tile, BK=16, 4x4 per thread, 256 threads.
// ---------------------------------------------------------------------------
__global__ void sgemm64(const float* __restrict__ A, const float* __restrict__ W,
                        float* __restrict__ C, int M, int N, int K) {
    __shared__ float As[16][68];
    __shared__ float Ws[16][64];
    const int bm = blockIdx.y * 64;
    const int bn = blockIdx.x * 64;
    const int t  = threadIdx.x;
    const int tx = t & 15, ty = t >> 4;

    float acc[4][4] = {};

    for (int k0 = 0; k0 < K; k0 += 16) {
        {   // A tile: 64 rows x 16 cols
            int r = t >> 2, c4 = (t & 3) * 4;
            float4 a = *reinterpret_cast<const float4*>(A + (size_t)(bm + r) * K + k0 + c4);
            As[c4 + 0][r] = a.x; As[c4 + 1][r] = a.y;
            As[c4 + 2][r] = a.z; As[c4 + 3][r] = a.w;
        }
        {   // W tile: 16 rows x 64 cols
            int r = t >> 4, c4 = (t & 15) * 4;
            *reinterpret_cast<float4*>(&Ws[r][c4]) =
                *reinterpret_cast<const float4*>(W + (size_t)(k0 + r) * N + bn + c4);
        }
        __syncthreads();
#pragma unroll
        for (int k = 0; k < 16; k++) {
            float4 a4 = *reinterpret_cast<const float4*>(&As[k][ty * 4]);
            float4 b4 = *reinterpret_cast<const float4*>(&Ws[k][tx * 4]);
            float a[4] = {a4.x, a4.y, a4.z, a4.w};
            float b[4] = {b4.x, b4.y, b4.z, b4.w};
#pragma unroll
            for (int i = 0; i < 4; i++)
#pragma unroll
                for (int j = 0; j < 4; j++) acc[i][j] += a[i] * b[j];
        }
        __syncthreads();
    }
#pragma unroll
    for (int i = 0; i < 4; i++) {
        float4 o = {acc[i][0], acc[i][1], acc[i][2], acc[i][3]};
        *reinterpret_cast<float4*>(C + (size_t)(bm + ty * 4 + i) * N + bn + tx * 4) = o;
    }
}

// ---------------------------------------------------------------------------
// Edge pass A: logits + per-(dst,head) max.  One warp per edge.
// ---------------------------------------------------------------------------
template <int C, int H, bool HAS_EF>
__global__ void edge_logits(const float* __restrict__ q, const float* __restrict__ k,
                            const float* __restrict__ ef,
                            const int* __restrict__ src, const int* __restrict__ dst,
                            float* __restrict__ logits, float* __restrict__ maxbuf,
                            int E, float scale) {
    constexpr int Oh = C / H;
    int warp = (blockIdx.x * blockDim.x + threadIdx.x) >> 5;
    int lane = threadIdx.x & 31;
    if (warp >= E) return;
    int s = src[warp], d = dst[warp];
    const float* qd  = q + (size_t)d * C;
    const float* ks  = k + (size_t)s * C;
    const float* efe = HAS_EF ? (ef + (size_t)warp * C) : nullptr;
#pragma unroll
    for (int h = 0; h < H; h++) {
        float p = 0.f;
#pragma unroll
        for (int c = lane; c < Oh; c += 32) {
            float kk = ks[h * Oh + c];
            if (HAS_EF) kk += efe[h * Oh + c];
            p += qd[h * Oh + c] * kk;
        }
#pragma unroll
        for (int o = 16; o > 0; o >>= 1) p += __shfl_down_sync(0xffffffffu, p, o);
        if (lane == 0) {
            float l = p * scale;
            l = (l > 0.f) ? l : 0.2f * l;          // leaky_relu(., 0.2)
            logits[(size_t)warp * H + h] = l;
            atomicMaxF(&maxbuf[(size_t)d * H + h], l);
        }
    }
}

// ---------------------------------------------------------------------------
// Edge pass B: w = exp(l - m); sum[dst,h] += w; acc[dst,:] += w * (v[src]+ef)
// ---------------------------------------------------------------------------
template <int C, int H, bool HAS_EF>
__global__ void edge_accum(const float* __restrict__ v, const float* __restrict__ ef,
                           const int* __restrict__ src, const int* __restrict__ dst,
                           const float* __restrict__ logits, const float* __restrict__ maxbuf,
                           float* __restrict__ sumbuf, float* __restrict__ acc, int E) {
    constexpr int Oh = C / H;
    int warp = (blockIdx.x * blockDim.x + threadIdx.x) >> 5;
    int lane = threadIdx.x & 31;
    if (warp >= E) return;
    int s = src[warp], d = dst[warp];
    float ww = 0.f;
    if (lane < H) {
        float l = logits[(size_t)warp * H + lane];
        float m = maxbuf[(size_t)d * H + lane];
        ww = expf(l - m);
        atomicAdd(&sumbuf[(size_t)d * H + lane], ww);
    }
    const float* vs  = v + (size_t)s * C;
    const float* efe = HAS_EF ? (ef + (size_t)warp * C) : nullptr;
    float* ad = acc + (size_t)d * C;
#pragma unroll
    for (int c = lane; c < C; c += 32) {
        float wh = __shfl_sync(0xffffffffu, ww, c / Oh);
        float vv = vs[c];
        if (HAS_EF) vv += efe[c];
        atomicAdd(&ad[c], wh * vv);
    }
}

// ---------------------------------------------------------------------------
// Node finalize: out = acc / (sum + 1e-16); accumulate BN sum/sumsq per channel
// ---------------------------------------------------------------------------
template <int C, int H>
__global__ void node_finalize(float* __restrict__ acc, const float* __restrict__ sumbuf,
                              float* __restrict__ bnsum, float* __restrict__ bnsq) {
    constexpr int Oh = C / H;
    constexpr int RPB = 64;                  // rows per block
    int c  = threadIdx.x % C;
    int r0 = blockIdx.x * RPB + threadIdx.x / C;
    int rstep = blockDim.x / C;
    int rend  = blockIdx.x * RPB + RPB;
    float s = 0.f, ss = 0.f;
    for (int r = r0; r < rend; r += rstep) {
        float denom = sumbuf[(size_t)r * H + c / Oh] + 1e-16f;
        float o = acc[(size_t)r * C + c] / denom;
        acc[(size_t)r * C + c] = o;
        s += o; ss += o * o;
    }
    atomicAdd(&bnsum[c], s);
    atomicAdd(&bnsq[c], ss);
}

__global__ void bn_final(const float* __restrict__ bnsum, const float* __restrict__ bnsq,
                         float* __restrict__ mu, float* __restrict__ rstd, int Nrows, int C) {
    int c = threadIdx.x;
    if (c < C) {
        float m = bnsum[c] / (float)Nrows;
        float v = bnsq[c] / (float)Nrows - m * m;
        mu[c] = m;
        rstd[c] = rsqrtf(v + 1e-5f);
    }
}

// relu(bn(o)) then residual (+ or -)
template <int C, bool SUB>
__global__ void bn_apply(const float* __restrict__ o, const float* __restrict__ res,
                         const float* __restrict__ mu, const float* __restrict__ rstd,
                         const float* __restrict__ g, const float* __restrict__ b,
                         float* __restrict__ out, int nelem) {
    int i = blockIdx.x * blockDim.x + threadIdx.x;
    if (i >= nelem) return;
    int c = i % C;
    float y = (o[i] - mu[c]) * rstd[c] * g[c] + b[c];
    y = fmaxf(y, 0.f);
    out[i] = SUB ? (res[i] - y) : (res[i] + y);
}

// ---------------------------------------------------------------------------
// BatchReversalToEdge
// ---------------------------------------------------------------------------
__global__ void to_edge(const float* __restrict__ br, float* __restrict__ ei) {
    int i = blockIdx.x * blockDim.x + threadIdx.x;
    if (i >= NN_EDGES * CE) return;
    int c = i % CE, row = i / CE;
    int g = row / EPG, r = row % EPG;
    float val;
    if (r < 2 * CNUM)             val = br[((size_t)g * MPG + (r >> 1)) * CE + c];
    else if (r < 2 * CNUM + NPG)  val = (c == 0) ? 1.f : 0.f;
    else                          val = br[((size_t)g * MPG + CNUM + (r - 2 * CNUM - NPG)) * CE + c];
    ei[i] = val;
}

__global__ void super_node_k(const float* __restrict__ out2, float* __restrict__ sn) {
    int i = blockIdx.x * blockDim.x + threadIdx.x;
    if (i >= BGR * CN) return;
    int g = i / CN, c = i % CN;
    sn[i] = out2[((size_t)g * NPG + NPG - 1) * CN + c];
}

// ---------------------------------------------------------------------------
// Host orchestration
// ---------------------------------------------------------------------------
static inline float* sym(const void* s) {
    void* p = nullptr;
    cudaGetSymbolAddress(&p, (const void*)s);
    return (float*)p;
}

extern "C" void kernel_launch(void* const* d_in, const int* in_sizes, int n_in,
                              void* d_out, int out_size) {
    (void)in_sizes; (void)n_in; (void)out_size;
    const float* x    = (const float*)d_in[0];
    const int*   eiN  = (const int*)d_in[1];
    const float* brf  = (const float*)d_in[2];
    const int*   eiE  = (const int*)d_in[3];
    const float* WqE1 = (const float*)d_in[4];
    const float* WkE1 = (const float*)d_in[5];
    const float* WvE1 = (const float*)d_in[6];
    const float* gE1  = (const float*)d_in[7];
    const float* bE1  = (const float*)d_in[8];
    const float* Wq1  = (const float*)d_in[9];
    const float* Wk1  = (const float*)d_in[10];
    const float* Wv1  = (const float*)d_in[11];
    const float* We1  = (const float*)d_in[12];
    const float* gN1  = (const float*)d_in[13];
    const float* bN1  = (const float*)d_in[14];
    const float* WqE2 = (const float*)d_in[15];
    const float* WkE2 = (const float*)d_in[16];
    const float* WvE2 = (const float*)d_in[17];
    const float* gE2  = (const float*)d_in[18];
    const float* bE2  = (const float*)d_in[19];
    const float* Wq2  = (const float*)d_in[20];
    const float* Wk2  = (const float*)d_in[21];
    const float* Wv2  = (const float*)d_in[22];
    const float* We2  = (const float*)d_in[23];
    const float* gN2  = (const float*)d_in[24];
    const float* bN2  = (const float*)d_in[25];

    float* out = (float*)d_out;
    float* out2_buf = out + OFF_OUT2;
    float* ei2_buf  = out + OFF_EI;
    float* br2_buf  = out + OFF_BR;
    float* sn_buf   = out + OFF_SN;

    float* qE   = sym(g_qE);   float* kE   = sym(g_kE);   float* vE  = sym(g_vE);
    float* accE = sym(g_accE); float* br1  = sym(g_br1);  float* logE = sym(g_logE);
    float* maxE = sym(g_maxE); float* sumE = sym(g_sumE);
    float* ei1  = sym(g_ei1);  float* ef   = sym(g_ef);
    float* qN   = sym(g_qN);   float* kN   = sym(g_kN);   float* vN  = sym(g_vN);
    float* accN = sym(g_accN); float* out1 = sym(g_out1); float* logN = sym(g_logN);
    float* maxN = sym(g_maxN); float* sumN = sym(g_sumN);
    float* bnsum = sym(g_bnsum); float* bnsq = sym(g_bnsq);
    float* mu = sym(g_mu);       float* rstd = sym(g_rstd);

    const int* srcE = eiE;              const int* dstE = eiE + NE_EDGES;
    const int* srcN = eiN;              const int* dstN = eiN + NN_EDGES;

    const float NEG_INF = -INFINITY;
    const float scaleE = 0.25f;    // 1/sqrt(16)
    const float scaleN = 0.125f;   // 1/sqrt(64)

    dim3 gemmE(CE / 64, NE_NODES / 64);    // 1 x 1024
    dim3 gemmN(CN / 64, NN_NODES / 64);    // 4 x 512
    dim3 gemmF(CN / 64, NN_EDGES / 64);    // 4 x 1600
    int ebE = NE_EDGES / 8, ebN = NN_EDGES / 8;   // warp-per-edge, 8 warps/block

    // =============== E1: conv_E(br) -> bn -> relu -> +br ===============
    sgemm64<<<gemmE, 256>>>(brf, WqE1, qE, NE_NODES, CE, CE);
    sgemm64<<<gemmE, 256>>>(brf, WkE1, kE, NE_NODES, CE, CE);
    sgemm64<<<gemmE, 256>>>(brf, WvE1, vE, NE_NODES, CE, CE);
    fill_f<<<(NE_NODES * 4 + 255) / 256, 256>>>(maxE, NE_NODES * 4, NEG_INF);
    cudaMemsetAsync(sumE, 0, (size_t)NE_NODES * 4 * 4);
    cudaMemsetAsync(accE, 0, (size_t)NE_NODES * CE * 4);
    cudaMemsetAsync(bnsum, 0, CN * 4);
    cudaMemsetAsync(bnsq, 0, CN * 4);
    edge_logits<CE, 4, false><<<ebE, 256>>>(qE, kE, nullptr, srcE, dstE, logE, maxE, NE_EDGES, scaleE);
    edge_accum<CE, 4, false><<<ebE, 256>>>(vE, nullptr, srcE, dstE, logE, maxE, sumE, accE, NE_EDGES);
    node_finalize<CE, 4><<<NE_NODES / 64, 256>>>(accE, sumE, bnsum, bnsq);
    bn_final<<<1, 256>>>(bnsum, bnsq, mu, rstd, NE_NODES, CE);
    bn_apply<CE, false><<<(NE_NODES * CE) / 256, 256>>>(accE, brf, mu, rstd, gE1, bE1, br1, NE_NODES * CE);

    // =============== to_edge(br1) -> ei1, ef1 = ei1 @ We1 ===============
    to_edge<<<(NN_EDGES * CE) / 256, 256>>>(br1, ei1);
    sgemm64<<<gemmF, 256>>>(ei1, We1, ef, NN_EDGES, CN, CE);

    // =============== N1: conv_N(x, ef1) -> bn -> relu -> +x ===============
    sgemm64<<<gemmN, 256>>>(x, Wq1, qN, NN_NODES, CN, CN);
    sgemm64<<<gemmN, 256>>>(x, Wk1, kN, NN_NODES, CN, CN);
    sgemm64<<<gemmN, 256>>>(x, Wv1, vN, NN_NODES, CN, CN);
    fill_f<<<(NN_NODES * 4 + 255) / 256, 256>>>(maxN, NN_NODES * 4, NEG_INF);
    cudaMemsetAsync(sumN, 0, (size_t)NN_NODES * 4 * 4);
    cudaMemsetAsync(accN, 0, (size_t)NN_NODES * CN * 4);
    cudaMemsetAsync(bnsum, 0, CN * 4);
    cudaMemsetAsync(bnsq, 0, CN * 4);
    edge_logits<CN, 4, true><<<ebN, 256>>>(qN, kN, ef, srcN, dstN, logN, maxN, NN_EDGES, scaleN);
    edge_accum<CN, 4, true><<<ebN, 256>>>(vN, ef, srcN, dstN, logN, maxN, sumN, accN, NN_EDGES);
    node_finalize<CN, 4><<<NN_NODES / 64, 256>>>(accN, sumN, bnsum, bnsq);
    bn_final<<<1, 256>>>(bnsum, bnsq, mu, rstd, NN_NODES, CN);
    bn_apply<CN, false><<<(NN_NODES * CN) / 256, 256>>>(accN, x, mu, rstd, gN1, bN1, out1, NN_NODES * CN);

    // =============== E2: conv_E(br1) -> bn -> relu; br2 = br1 - o ===============
    sgemm64<<<gemmE, 256>>>(br1, WqE2, qE, NE_NODES, CE, CE);
    sgemm64<<<gemmE, 256>>>(br1, WkE2, kE, NE_NODES, CE, CE);
    sgemm64<<<gemmE, 256>>>(br1, WvE2, vE, NE_NODES, CE, CE);
    fill_f<<<(NE_NODES * 4 + 255) / 256, 256>>>(maxE, NE_NODES * 4, NEG_INF);
    cudaMemsetAsync(sumE, 0, (size_t)NE_NODES * 4 * 4);
    cudaMemsetAsync(accE, 0, (size_t)NE_NODES * CE * 4);
    cudaMemsetAsync(bnsum, 0, CN * 4);
    cudaMemsetAsync(bnsq, 0, CN * 4);
    edge_logits<CE, 4, false><<<ebE, 256>>>(qE, kE, nullptr, srcE, dstE, logE, maxE, NE_EDGES, scaleE);
    edge_accum<CE, 4, false><<<ebE, 256>>>(vE, nullptr, srcE, dstE, logE, maxE, sumE, accE, NE_EDGES);
    node_finalize<CE, 4><<<NE_NODES / 64, 256>>>(accE, sumE, bnsum, bnsq);
    bn_final<<<1, 256>>>(bnsum, bnsq, mu, rstd, NE_NODES, CE);
    bn_apply<CE, true><<<(NE_NODES * CE) / 256, 256>>>(accE, br1, mu, rstd, gE2, bE2, br2_buf, NE_NODES * CE);

    // =============== to_edge(br2) -> ei2 (output), ef2 = ei2 @ We2 ===============
    to_edge<<<(NN_EDGES * CE) / 256, 256>>>(br2_buf, ei2_buf);
    sgemm64<<<gemmF, 256>>>(ei2_buf, We2, ef, NN_EDGES, CN, CE);

    // =============== N2: conv_N(out1, ef2) -> bn -> relu; out2 = out1 - o ===============
    sgemm64<<<gemmN, 256>>>(out1, Wq2, qN, NN_NODES, CN, CN);
    sgemm64<<<gemmN, 256>>>(out1, Wk2, kN, NN_NODES, CN, CN);
    sgemm64<<<gemmN, 256>>>(out1, Wv2, vN, NN_NODES, CN, CN);
    fill_f<<<(NN_NODES * 4 + 255) / 256, 256>>>(maxN, NN_NODES * 4, NEG_INF);
    cudaMemsetAsync(sumN, 0, (size_t)NN_NODES * 4 * 4);
    cudaMemsetAsync(accN, 0, (size_t)NN_NODES * CN * 4);
    cudaMemsetAsync(bnsum, 0, CN * 4);
    cudaMemsetAsync(bnsq, 0, CN * 4);
    edge_logits<CN, 4, true><<<ebN, 256>>>(qN, kN, ef, srcN, dstN, logN, maxN, NN_EDGES, scaleN);
    edge_accum<CN, 4, true><<<ebN, 256>>>(vN, ef, srcN, dstN, logN, maxN, sumN, accN, NN_EDGES);
    node_finalize<CN, 4><<<NN_NODES / 64, 256>>>(accN, sumN, bnsum, bnsq);
    bn_final<<<1, 256>>>(bnsum, bnsq, mu, rstd, NN_NODES, CN);
    bn_apply<CN, true><<<(NN_NODES * CN) / 256, 256>>>(accN, out1, mu, rstd, gN2, bN2, out2_buf, NN_NODES * CN);

    // =============== super node ===============
    super_node_k<<<(BGR * CN) / 256, 256>>>(out2_buf, sn_buf);
}

// round 3
// speedup vs baseline: 1.2130x; 1.2130x over previous
#include <cuda_runtime.h>
#include <cstdint>
#include <cstring>
#include <math.h>

// ---------------------------------------------------------------------------
// Problem constants
// ---------------------------------------------------------------------------
#define BGR   512
#define NPG   64
#define CNUM  8
#define MPG   128
#define CN    256
#define CE    64
#define EPG   200            // MPG + CNUM + NPG

#define NE_NODES (BGR*MPG)        // 65536 br nodes
#define NE_EDGES (BGR*MPG*4)      // 262144 br edges
#define NN_NODES (BGR*NPG)        // 32768 nodes
#define NN_EDGES (BGR*EPG)        // 102400 edges

// output layout: out2 | ei | br | super_node
#define OFF_OUT2 0
#define OFF_EI   ((size_t)NN_NODES*CN)
#define OFF_BR   (OFF_EI + (size_t)NN_EDGES*CE)
#define OFF_SN   (OFF_BR + (size_t)NE_NODES*CE)

// ---------------------------------------------------------------------------
// Scratch (device globals: allocation-free)
// ---------------------------------------------------------------------------
__device__ float g_qE[(size_t)NE_NODES*CE];
__device__ float g_kE[(size_t)NE_NODES*CE];
__device__ float g_vE[(size_t)NE_NODES*CE];
__device__ float g_accE[(size_t)NE_NODES*CE];
__device__ float g_br1[(size_t)NE_NODES*CE];
__device__ float g_logE[(size_t)NE_EDGES*4];
__device__ float g_maxE[(size_t)NE_NODES*4];
__device__ float g_sumE[(size_t)NE_NODES*4];

__device__ float g_ei1[(size_t)NN_EDGES*CE];
__device__ float g_ef[(size_t)NN_EDGES*CN];
__device__ float g_qN[(size_t)NN_NODES*CN];
__device__ float g_kN[(size_t)NN_NODES*CN];
__device__ float g_vN[(size_t)NN_NODES*CN];
__device__ float g_accN[(size_t)NN_NODES*CN];
__device__ float g_out1[(size_t)NN_NODES*CN];
__device__ float g_logN[(size_t)NN_EDGES*4];
__device__ float g_maxN[(size_t)NN_NODES*4];
__device__ float g_sumN[(size_t)NN_NODES*4];

__device__ float g_bnsum[CN];
__device__ float g_bnsq[CN];
__device__ float g_mu[CN];
__device__ float g_rstd[CN];

// ---------------------------------------------------------------------------
// Helpers
// ---------------------------------------------------------------------------
__device__ __forceinline__ void atomicMaxF(float* addr, float v) {
    if (v >= 0.f) atomicMax((int*)addr, __float_as_int(v));
    else          atomicMin((unsigned int*)addr, __float_as_uint(v));
}

__global__ void fill_f(float* p, int n, float v) {
    int i = blockIdx.x * blockDim.x + threadIdx.x;
    if (i < n) p[i] = v;
}

// ---------------------------------------------------------------------------
// Fused QKV SGEMM with packed f32x2 FMA.
// C{0,1,2}[M,Nper] = A[M,K] @ W{0,1,2}[K,Nper]
// 128 x TN block tile, BK=8, double-buffered, 256 threads, 8x(TN/16)/thread.
// For a single GEMM pass W0=W1=W2, C0=C1=C2 and grid.x = Nper/TN.
// ---------------------------------------------------------------------------
template<int TN>
__global__ void __launch_bounds__(256, 2) gemm_qkv(
    const float* __restrict__ A,
    const float* __restrict__ W0, const float* __restrict__ W1, const float* __restrict__ W2,
    float* __restrict__ C0, float* __restrict__ C1, float* __restrict__ C2,
    int M, int Nper, int K)
{
    constexpr int BK = 8;
    constexpr int NG = TN / 64;               // column groups of 64
    __shared__ float As[2][BK][128];
    __shared__ float Bs[2][BK][TN];

    const int nb  = Nper / TN;
    const int mat = blockIdx.x / nb;
    const int bn  = (blockIdx.x - mat * nb) * TN;
    const float* __restrict__ W = (mat == 0) ? W0 : ((mat == 1) ? W1 : W2);
    float* __restrict__ C       = (mat == 0) ? C0 : ((mat == 1) ? C1 : C2);
    const int bm = blockIdx.y * 128;
    const int t  = threadIdx.x;
    const int tx = t & 15, ty = t >> 4;

    // A tile load mapping: 128 rows x 8 cols, one float4 per thread
    const int ar = t >> 1, ac = (t & 1) * 4;
    const float* Ag = A + (size_t)(bm + ar) * K + ac;
    // B tile load mapping: BK rows x TN cols, float4 per thread (first BT threads)
    constexpr int BT = TN * BK / 4;           // 256 (TN=128) or 128 (TN=64)
    const int brow = t / (TN / 4);
    const int bcol = (t % (TN / 4)) * 4;
    const float* Wg = W + (size_t)brow * Nper + bn + bcol;

    unsigned long long acc[8][2 * NG];
#pragma unroll
    for (int i = 0; i < 8; i++)
#pragma unroll
        for (int j = 0; j < 2 * NG; j++) acc[i][j] = 0ull;

    // prologue: stage 0
    {
        float4 a = *reinterpret_cast<const float4*>(Ag);
        As[0][ac + 0][ar] = a.x; As[0][ac + 1][ar] = a.y;
        As[0][ac + 2][ar] = a.z; As[0][ac + 3][ar] = a.w;
        if (t < BT)
            *reinterpret_cast<float4*>(&Bs[0][brow][bcol]) =
                *reinterpret_cast<const float4*>(Wg);
    }
    __syncthreads();

    int buf = 0;
    for (int k0 = 0; k0 < K; k0 += BK) {
        float4 apre; float4 bpre;
        const bool nxt = (k0 + BK) < K;
        if (nxt) {
            apre = *reinterpret_cast<const float4*>(Ag + k0 + BK);
            if (t < BT)
                bpre = *reinterpret_cast<const float4*>(Wg + (size_t)(k0 + BK) * Nper);
        }
#pragma unroll
        for (int k = 0; k < BK; k++) {
            float4 a0 = *reinterpret_cast<const float4*>(&As[buf][k][ty * 4]);
            float4 a1 = *reinterpret_cast<const float4*>(&As[buf][k][64 + ty * 4]);
            float ar8[8] = {a0.x, a0.y, a0.z, a0.w, a1.x, a1.y, a1.z, a1.w};
            unsigned long long av[8];
#pragma unroll
            for (int i = 0; i < 8; i++)
                asm("mov.b64 %0, {%1, %1};" : "=l"(av[i]) : "f"(ar8[i]));
            unsigned long long bv[2 * NG];
#pragma unroll
            for (int g = 0; g < NG; g++) {
                ulonglong2 b2 = *reinterpret_cast<const ulonglong2*>(&Bs[buf][k][g * 64 + tx * 4]);
                bv[2 * g] = b2.x; bv[2 * g + 1] = b2.y;
            }
#pragma unroll
            for (int i = 0; i < 8; i++)
#pragma unroll
                for (int j = 0; j < 2 * NG; j++)
                    asm("fma.rn.f32x2 %0, %1, %2, %0;"
                        : "+l"(acc[i][j]) : "l"(av[i]), "l"(bv[j]));
        }
        if (nxt) {
            As[buf ^ 1][ac + 0][ar] = apre.x; As[buf ^ 1][ac + 1][ar] = apre.y;
            As[buf ^ 1][ac + 2][ar] = apre.z; As[buf ^ 1][ac + 3][ar] = apre.w;
            if (t < BT)
                *reinterpret_cast<float4*>(&Bs[buf ^ 1][brow][bcol]) = bpre;
            __syncthreads();
            buf ^= 1;
        }
    }

    // epilogue: unpack pairs, vectorized stores
#pragma unroll
    for (int i = 0; i < 8; i++) {
        int row = bm + ((i < 4) ? (ty * 4 + i) : (64 + ty * 4 + (i - 4)));
        float* Crow = C + (size_t)row * Nper + bn;
#pragma unroll
        for (int g = 0; g < NG; g++) {
            float4 o;
            asm("mov.b64 {%0, %1}, %2;" : "=f"(o.x), "=f"(o.y) : "l"(acc[i][2 * g]));
            asm("mov.b64 {%0, %1}, %2;" : "=f"(o.z), "=f"(o.w) : "l"(acc[i][2 * g + 1]));
            *reinterpret_cast<float4*>(Crow + g * 64 + tx * 4) = o;
        }
    }
}

// ---------------------------------------------------------------------------
// Edge pass A: logits + per-(dst,head) max.  One warp per edge.
// ---------------------------------------------------------------------------
template <int C, int H, bool HAS_EF>
__global__ void edge_logits(const float* __restrict__ q, const float* __restrict__ k,
                            const float* __restrict__ ef,
                            const int* __restrict__ src, const int* __restrict__ dst,
                            float* __restrict__ logits, float* __restrict__ maxbuf,
                            int E, float scale) {
    constexpr int Oh = C / H;
    int warp = (blockIdx.x * blockDim.x + threadIdx.x) >> 5;
    int lane = threadIdx.x & 31;
    if (warp >= E) return;
    int s = src[warp], d = dst[warp];
    const float* qd  = q + (size_t)d * C;
    const float* ks  = k + (size_t)s * C;
    const float* efe = HAS_EF ? (ef + (size_t)warp * C) : nullptr;
#pragma unroll
    for (int h = 0; h < H; h++) {
        float p = 0.f;
#pragma unroll
        for (int c = lane; c < Oh; c += 32) {
            float kk = ks[h * Oh + c];
            if (HAS_EF) kk += efe[h * Oh + c];
            p += qd[h * Oh + c] * kk;
        }
#pragma unroll
        for (int o = 16; o > 0; o >>= 1) p += __shfl_down_sync(0xffffffffu, p, o);
        if (lane == 0) {
            float l = p * scale;
            l = (l > 0.f) ? l : 0.2f * l;          // leaky_relu(., 0.2)
            logits[(size_t)warp * H + h] = l;
            atomicMaxF(&maxbuf[(size_t)d * H + h], l);
        }
    }
}

// ---------------------------------------------------------------------------
// Edge pass B: w = exp(l - m); sum[dst,h] += w; acc[dst,:] += w * (v[src]+ef)
// ---------------------------------------------------------------------------
template <int C, int H, bool HAS_EF>
__global__ void edge_accum(const float* __restrict__ v, const float* __restrict__ ef,
                           const int* __restrict__ src, const int* __restrict__ dst,
                           const float* __restrict__ logits, const float* __restrict__ maxbuf,
                           float* __restrict__ sumbuf, float* __restrict__ acc, int E) {
    constexpr int Oh = C / H;
    int warp = (blockIdx.x * blockDim.x + threadIdx.x) >> 5;
    int lane = threadIdx.x & 31;
    if (warp >= E) return;
    int s = src[warp], d = dst[warp];
    float ww = 0.f;
    if (lane < H) {
        float l = logits[(size_t)warp * H + lane];
        float m = maxbuf[(size_t)d * H + lane];
        ww = expf(l - m);
        atomicAdd(&sumbuf[(size_t)d * H + lane], ww);
    }
    const float* vs  = v + (size_t)s * C;
    const float* efe = HAS_EF ? (ef + (size_t)warp * C) : nullptr;
    float* ad = acc + (size_t)d * C;
#pragma unroll
    for (int c = lane; c < C; c += 32) {
        float wh = __shfl_sync(0xffffffffu, ww, c / Oh);
        float vv = vs[c];
        if (HAS_EF) vv += efe[c];
        atomicAdd(&ad[c], wh * vv);
    }
}

// ---------------------------------------------------------------------------
// Node finalize: out = acc / (sum + 1e-16); accumulate BN sum/sumsq per channel
// ---------------------------------------------------------------------------
template <int C, int H>
__global__ void node_finalize(float* __restrict__ acc, const float* __restrict__ sumbuf,
                              float* __restrict__ bnsum, float* __restrict__ bnsq) {
    constexpr int Oh = C / H;
    constexpr int RPB = 64;                  // rows per block
    int c  = threadIdx.x % C;
    int r0 = blockIdx.x * RPB + threadIdx.x / C;
    int rstep = blockDim.x / C;
    int rend  = blockIdx.x * RPB + RPB;
    float s = 0.f, ss = 0.f;
    for (int r = r0; r < rend; r += rstep) {
        float denom = sumbuf[(size_t)r * H + c / Oh] + 1e-16f;
        float o = acc[(size_t)r * C + c] / denom;
        acc[(size_t)r * C + c] = o;
        s += o; ss += o * o;
    }
    atomicAdd(&bnsum[c], s);
    atomicAdd(&bnsq[c], ss);
}

__global__ void bn_final(const float* __restrict__ bnsum, const float* __restrict__ bnsq,
                         float* __restrict__ mu, float* __restrict__ rstd, int Nrows, int C) {
    int c = threadIdx.x;
    if (c < C) {
        float m = bnsum[c] / (float)Nrows;
        float v = bnsq[c] / (float)Nrows - m * m;
        mu[c] = m;
        rstd[c] = rsqrtf(v + 1e-5f);
    }
}

// relu(bn(o)) then residual (+ or -)
template <int C, bool SUB>
__global__ void bn_apply(const float* __restrict__ o, const float* __restrict__ res,
                         const float* __restrict__ mu, const float* __restrict__ rstd,
                         const float* __restrict__ g, const float* __restrict__ b,
                         float* __restrict__ out, int nelem) {
    int i = blockIdx.x * blockDim.x + threadIdx.x;
    if (i >= nelem) return;
    int c = i % C;
    float y = (o[i] - mu[c]) * rstd[c] * g[c] + b[c];
    y = fmaxf(y, 0.f);
    out[i] = SUB ? (res[i] - y) : (res[i] + y);
}

// ---------------------------------------------------------------------------
// BatchReversalToEdge
// ---------------------------------------------------------------------------
__global__ void to_edge(const float* __restrict__ br, float* __restrict__ ei) {
    int i = blockIdx.x * blockDim.x + threadIdx.x;
    if (i >= NN_EDGES * CE) return;
    int c = i % CE, row = i / CE;
    int g = row / EPG, r = row % EPG;
    float val;
    if (r < 2 * CNUM)             val = br[((size_t)g * MPG + (r >> 1)) * CE + c];
    else if (r < 2 * CNUM + NPG)  val = (c == 0) ? 1.f : 0.f;
    else                          val = br[((size_t)g * MPG + CNUM + (r - 2 * CNUM - NPG)) * CE + c];
    ei[i] = val;
}

__global__ void super_node_k(const float* __restrict__ out2, float* __restrict__ sn) {
    int i = blockIdx.x * blockDim.x + threadIdx.x;
    if (i >= BGR * CN) return;
    int g = i / CN, c = i % CN;
    sn[i] = out2[((size_t)g * NPG + NPG - 1) * CN + c];
}

// ---------------------------------------------------------------------------
// Host orchestration
// ---------------------------------------------------------------------------
static inline float* sym(const void* s) {
    void* p = nullptr;
    cudaGetSymbolAddress(&p, (const void*)s);
    return (float*)p;
}

extern "C" void kernel_launch(void* const* d_in, const int* in_sizes, int n_in,
                              void* d_out, int out_size) {
    (void)in_sizes; (void)n_in; (void)out_size;
    const float* x    = (const float*)d_in[0];
    const int*   eiN  = (const int*)d_in[1];
    const float* brf  = (const float*)d_in[2];
    const int*   eiE  = (const int*)d_in[3];
    const float* WqE1 = (const float*)d_in[4];
    const float* WkE1 = (const float*)d_in[5];
    const float* WvE1 = (const float*)d_in[6];
    const float* gE1  = (const float*)d_in[7];
    const float* bE1  = (const float*)d_in[8];
    const float* Wq1  = (const float*)d_in[9];
    const float* Wk1  = (const float*)d_in[10];
    const float* Wv1  = (const float*)d_in[11];
    const float* We1  = (const float*)d_in[12];
    const float* gN1  = (const float*)d_in[13];
    const float* bN1  = (const float*)d_in[14];
    const float* WqE2 = (const float*)d_in[15];
    const float* WkE2 = (const float*)d_in[16];
    const float* WvE2 = (const float*)d_in[17];
    const float* gE2  = (const float*)d_in[18];
    const float* bE2  = (const float*)d_in[19];
    const float* Wq2  = (const float*)d_in[20];
    const float* Wk2  = (const float*)d_in[21];
    const float* Wv2  = (const float*)d_in[22];
    const float* We2  = (const float*)d_in[23];
    const float* gN2  = (const float*)d_in[24];
    const float* bN2  = (const float*)d_in[25];

    float* out = (float*)d_out;
    float* out2_buf = out + OFF_OUT2;
    float* ei2_buf  = out + OFF_EI;
    float* br2_buf  = out + OFF_BR;
    float* sn_buf   = out + OFF_SN;

    float* qE   = sym(g_qE);   float* kE   = sym(g_kE);   float* vE  = sym(g_vE);
    float* accE = sym(g_accE); float* br1  = sym(g_br1);  float* logE = sym(g_logE);
    float* maxE = sym(g_maxE); float* sumE = sym(g_sumE);
    float* ei1  = sym(g_ei1);  float* ef   = sym(g_ef);
    float* qN   = sym(g_qN);   float* kN   = sym(g_kN);   float* vN  = sym(g_vN);
    float* accN = sym(g_accN); float* out1 = sym(g_out1); float* logN = sym(g_logN);
    float* maxN = sym(g_maxN); float* sumN = sym(g_sumN);
    float* bnsum = sym(g_bnsum); float* bnsq = sym(g_bnsq);
    float* mu = sym(g_mu);       float* rstd = sym(g_rstd);

    const int* srcE = eiE;              const int* dstE = eiE + NE_EDGES;
    const int* srcN = eiN;              const int* dstN = eiN + NN_EDGES;

    const float NEG_INF = -INFINITY;
    const float scaleE = 0.25f;    // 1/sqrt(16)
    const float scaleN = 0.125f;   // 1/sqrt(64)

    // fused qkv grids
    dim3 qkvE(3 * (CE / 64), NE_NODES / 128);   // TN=64 : 3 x 512
    dim3 qkvN(3 * (CN / 128), NN_NODES / 128);  // TN=128: 6 x 256
    dim3 efG(CN / 128, NN_EDGES / 128);         // TN=128: 2 x 800
    int ebE = NE_EDGES / 8, ebN = NN_EDGES / 8; // warp-per-edge, 8 warps/block

    // =============== E1: conv_E(br) -> bn -> relu -> +br ===============
    gemm_qkv<64><<<qkvE, 256>>>(brf, WqE1, WkE1, WvE1, qE, kE, vE, NE_NODES, CE, CE);
    fill_f<<<(NE_NODES * 4 + 255) / 256, 256>>>(maxE, NE_NODES * 4, NEG_INF);
    cudaMemsetAsync(sumE, 0, (size_t)NE_NODES * 4 * 4);
    cudaMemsetAsync(accE, 0, (size_t)NE_NODES * CE * 4);
    cudaMemsetAsync(bnsum, 0, CN * 4);
    cudaMemsetAsync(bnsq, 0, CN * 4);
    edge_logits<CE, 4, false><<<ebE, 256>>>(qE, kE, nullptr, srcE, dstE, logE, maxE, NE_EDGES, scaleE);
    edge_accum<CE, 4, false><<<ebE, 256>>>(vE, nullptr, srcE, dstE, logE, maxE, sumE, accE, NE_EDGES);
    node_finalize<CE, 4><<<NE_NODES / 64, 256>>>(accE, sumE, bnsum, bnsq);
    bn_final<<<1, 256>>>(bnsum, bnsq, mu, rstd, NE_NODES, CE);
    bn_apply<CE, false><<<(NE_NODES * CE) / 256, 256>>>(accE, brf, mu, rstd, gE1, bE1, br1, NE_NODES * CE);

    // =============== to_edge(br1) -> ei1, ef1 = ei1 @ We1 ===============
    to_edge<<<(NN_EDGES * CE) / 256, 256>>>(br1, ei1);
    gemm_qkv<128><<<efG, 256>>>(ei1, We1, We1, We1, ef, ef, ef, NN_EDGES, CN, CE);

    // =============== N1: conv_N(x, ef1) -> bn -> relu -> +x ===============
    gemm_qkv<128><<<qkvN, 256>>>(x, Wq1, Wk1, Wv1, qN, kN, vN, NN_NODES, CN, CN);
    fill_f<<<(NN_NODES * 4 + 255) / 256, 256>>>(maxN, NN_NODES * 4, NEG_INF);
    cudaMemsetAsync(sumN, 0, (size_t)NN_NODES * 4 * 4);
    cudaMemsetAsync(accN, 0, (size_t)NN_NODES * CN * 4);
    cudaMemsetAsync(bnsum, 0, CN * 4);
    cudaMemsetAsync(bnsq, 0, CN * 4);
    edge_logits<CN, 4, true><<<ebN, 256>>>(qN, kN, ef, srcN, dstN, logN, maxN, NN_EDGES, scaleN);
    edge_accum<CN, 4, true><<<ebN, 256>>>(vN, ef, srcN, dstN, logN, maxN, sumN, accN, NN_EDGES);
    node_finalize<CN, 4><<<NN_NODES / 64, 256>>>(accN, sumN, bnsum, bnsq);
    bn_final<<<1, 256>>>(bnsum, bnsq, mu, rstd, NN_NODES, CN);
    bn_apply<CN, false><<<(NN_NODES * CN) / 256, 256>>>(accN, x, mu, rstd, gN1, bN1, out1, NN_NODES * CN);

    // =============== E2: conv_E(br1) -> bn -> relu; br2 = br1 - o ===============
    gemm_qkv<64><<<qkvE, 256>>>(br1, WqE2, WkE2, WvE2, qE, kE, vE, NE_NODES, CE, CE);
    fill_f<<<(NE_NODES * 4 + 255) / 256, 256>>>(maxE, NE_NODES * 4, NEG_INF);
    cudaMemsetAsync(sumE, 0, (size_t)NE_NODES * 4 * 4);
    cudaMemsetAsync(accE, 0, (size_t)NE_NODES * CE * 4);
    cudaMemsetAsync(bnsum, 0, CN * 4);
    cudaMemsetAsync(bnsq, 0, CN * 4);
    edge_logits<CE, 4, false><<<ebE, 256>>>(qE, kE, nullptr, srcE, dstE, logE, maxE, NE_EDGES, scaleE);
    edge_accum<CE, 4, false><<<ebE, 256>>>(vE, nullptr, srcE, dstE, logE, maxE, sumE, accE, NE_EDGES);
    node_finalize<CE, 4><<<NE_NODES / 64, 256>>>(accE, sumE, bnsum, bnsq);
    bn_final<<<1, 256>>>(bnsum, bnsq, mu, rstd, NE_NODES, CE);
    bn_apply<CE, true><<<(NE_NODES * CE) / 256, 256>>>(accE, br1, mu, rstd, gE2, bE2, br2_buf, NE_NODES * CE);

    // =============== to_edge(br2) -> ei2 (output), ef2 = ei2 @ We2 ===============
    to_edge<<<(NN_EDGES * CE) / 256, 256>>>(br2_buf, ei2_buf);
    gemm_qkv<128><<<efG, 256>>>(ei2_buf, We2, We2, We2, ef, ef, ef, NN_EDGES, CN, CE);

    // =============== N2: conv_N(out1, ef2) -> bn -> relu; out2 = out1 - o ===============
    gemm_qkv<128><<<qkvN, 256>>>(out1, Wq2, Wk2, Wv2, qN, kN, vN, NN_NODES, CN, CN);
    fill_f<<<(NN_NODES * 4 + 255) / 256, 256>>>(maxN, NN_NODES * 4, NEG_INF);
    cudaMemsetAsync(sumN, 0, (size_t)NN_NODES * 4 * 4);
    cudaMemsetAsync(accN, 0, (size_t)NN_NODES * CN * 4);
    cudaMemsetAsync(bnsum, 0, CN * 4);
    cudaMemsetAsync(bnsq, 0, CN * 4);
    edge_logits<CN, 4, true><<<ebN, 256>>>(qN, kN, ef, srcN, dstN, logN, maxN, NN_EDGES, scaleN);
    edge_accum<CN, 4, true><<<ebN, 256>>>(vN, ef, srcN, dstN, logN, maxN, sumN, accN, NN_EDGES);
    node_finalize<CN, 4><<<NN_NODES / 64, 256>>>(accN, sumN, bnsum, bnsq);
    bn_final<<<1, 256>>>(bnsum, bnsq, mu, rstd, NN_NODES, CN);
    bn_apply<CN, true><<<(NN_NODES * CN) / 256, 256>>>(accN, out1, mu, rstd, gN2, bN2, out2_buf, NN_NODES * CN);

    // =============== super node ===============
    super_node_k<<<(BGR * CN) / 256, 256>>>(out2_buf, sn_buf);
}